// round 14
// baseline (speedup 1.0000x reference)
#include <cuda_runtime.h>
#include <cuda_fp16.h>
#include <cuda_bf16.h>

#define NMAX 100000
#define NPAD (98 * 1024)      // 100352: covers NMAX, int4-aligned 1024-chunks
#define EMAX 1600000
#define D 64
#define NCHUNK_MAX 98
#define TPB 256
#define GRID_BUILD 888        // 148 SMs x 6 CTAs co-resident under lb(256,6)

// __device__ scratch (no allocations allowed)
__device__ int    g_deg[NPAD];
__device__ int    g_rowstart[NPAD];
__device__ __half g_xh[(size_t)NMAX * D];
__device__ int    g_ecol[EMAX];
__device__ int    g_rank[EMAX];
__device__ volatile unsigned long long g_scan_pair[NCHUNK_MAX];

// software grid barrier (gen monotonic across replays; count self-resets)
__device__ unsigned g_bar_count;
__device__ volatile unsigned g_bar_gen;

__device__ __forceinline__ void grid_sync() {
    __threadfence();
    __syncthreads();
    if (threadIdx.x == 0) {
        unsigned gen = g_bar_gen;
        if (atomicAdd(&g_bar_count, 1u) == gridDim.x - 1) {
            g_bar_count = 0;
            __threadfence();
            g_bar_gen = gen + 1;
        } else {
            while (g_bar_gen == gen) { }
        }
    }
    __syncthreads();
    __threadfence();
}

// side stream + events for graph fork-join (created once; capture-legal)
static cudaStream_t g_s1;
static cudaEvent_t  g_ev_deg, g_ev_gemm;
namespace {
struct StreamInit {
    StreamInit() {
        cudaStreamCreateWithFlags(&g_s1, cudaStreamNonBlocking);
        cudaEventCreateWithFlags(&g_ev_deg, cudaEventDisableTiming);
        cudaEventCreateWithFlags(&g_ev_gemm, cudaEventDisableTiming);
    }
} g_stream_init;
}

// packed fp32x2 FMA (Blackwell)
__device__ __forceinline__ void fma_f32x2(unsigned long long& d,
                                          unsigned long long a,
                                          unsigned long long b,
                                          unsigned long long c) {
    asm("fma.rn.f32x2 %0, %1, %2, %3;" : "=l"(d) : "l"(a), "l"(b), "l"(c));
}
__device__ __forceinline__ unsigned smem_u32(const void* p) {
    return (unsigned)__cvta_generic_to_shared(p);
}
__device__ __forceinline__ void cp_async16(unsigned s, const void* g) {
    asm volatile("cp.async.cg.shared.global [%0], [%1], 16;" :: "r"(s), "l"(g));
}
__device__ __forceinline__ void cp_commit() { asm volatile("cp.async.commit_group;"); }
template <int N> __device__ __forceinline__ void cp_wait() {
    asm volatile("cp.async.wait_group %0;" :: "n"(N));
}

// ---------------------------------------------------------------------------
// Kernel A: zero -> [grid barrier] -> degree histogram + per-edge rank
// ---------------------------------------------------------------------------
__global__ void __launch_bounds__(TPB, 6) k_pre(const int* __restrict__ ei,
                                                int E, int N) {
    const int gid  = blockIdx.x * TPB + threadIdx.x;
    const int nthr = gridDim.x * TPB;

    for (int i = gid; i < NPAD; i += nthr) g_deg[i] = 0;
    if (gid < NCHUNK_MAX) g_scan_pair[gid] = 0ULL;
    grid_sync();

    const int E4 = E >> 2;
    const int4* rp4 = reinterpret_cast<const int4*>(ei);
    int4* rk4 = reinterpret_cast<int4*>(g_rank);
    for (int q = gid; q < E4; q += nthr) {
        int4 r = __ldg(rp4 + q);
        int4 k;
        k.x = atomicAdd(&g_deg[r.x], 1);
        k.y = atomicAdd(&g_deg[r.y], 1);
        k.z = atomicAdd(&g_deg[r.z], 1);
        k.w = atomicAdd(&g_deg[r.w], 1);
        rk4[q] = k;
    }
    for (int e = (E4 << 2) + gid; e < E; e += nthr)
        g_rank[e] = atomicAdd(&g_deg[__ldg(ei + e)], 1);
}

// ---------------------------------------------------------------------------
// Kernel B: scan (first 98 blocks) -> [grid barrier] -> CSR fill (no atomics)
// ---------------------------------------------------------------------------
__global__ void __launch_bounds__(TPB, 6) k_csr(const int* __restrict__ ei,
                                                int E, int N) {
    __shared__ int sh_wsum[8];
    __shared__ int sh_base;

    const int tid  = threadIdx.x;
    const int bid  = blockIdx.x;
    const int gid  = bid * TPB + tid;
    const int nthr = gridDim.x * TPB;
    const int lane = tid & 31;
    const int wid  = tid >> 5;
    const int nchunk = (N + 1023) >> 10;

    if (bid < nchunk) {
        int base = (bid << 10) + (tid << 2);
        int4 d = *reinterpret_cast<const int4*>(&g_deg[base]);   // padded, safe
        int s1 = d.x + d.y;
        int s2 = s1 + d.z;
        int tsum = s2 + d.w;

        int inc = tsum;
#pragma unroll
        for (int off = 1; off < 32; off <<= 1) {
            int t = __shfl_up_sync(0xffffffffu, inc, off);
            if (lane >= off) inc += t;
        }
        if (lane == 31) sh_wsum[wid] = inc;
        __syncthreads();
        if (wid == 0) {
            int v8 = (lane < 8) ? sh_wsum[lane] : 0;
#pragma unroll
            for (int off = 1; off < 8; off <<= 1) {
                int t = __shfl_up_sync(0xffffffffu, v8, off);
                if (lane >= off) v8 += t;
            }
            if (lane < 8) sh_wsum[lane] = v8;
        }
        __syncthreads();
        int texcl = inc - tsum + ((wid > 0) ? sh_wsum[wid - 1] : 0);
        int block_total = sh_wsum[7];

        if (wid == 0) {
            if (bid == 0) {
                if (lane == 0) {
                    g_scan_pair[0] = (2ULL << 32) | (unsigned)block_total;
                    sh_base = 0;
                }
            } else {
                if (lane == 0)
                    g_scan_pair[bid] = (1ULL << 32) | (unsigned)block_total;
                __syncwarp();
                int bacc = 0;
                int wstart = bid - 1;
                while (true) {
                    int j = wstart - lane;
                    unsigned flag = 0, val = 0;
                    if (j >= 0) {
                        unsigned long long p;
                        do { p = g_scan_pair[j]; } while ((p >> 32) == 0ULL);
                        flag = (unsigned)(p >> 32);
                        val = (unsigned)p;
                    }
                    unsigned b2 = __ballot_sync(0xffffffffu, flag == 2u);
                    if (b2) {
                        int lp = __ffs(b2) - 1;
                        unsigned contrib = (lane <= lp) ? val : 0u;
                        bacc += (int)__reduce_add_sync(0xffffffffu, contrib);
                        break;
                    } else {
                        bacc += (int)__reduce_add_sync(0xffffffffu, val);
                        wstart -= 32;
                    }
                }
                if (lane == 0) {
                    g_scan_pair[bid] = (2ULL << 32) | (unsigned)(bacc + block_total);
                    sh_base = bacc;
                }
            }
        }
        __syncthreads();

        int S = sh_base + texcl;
        int4 o;
        o.x = S;
        o.y = S + d.x;
        o.z = S + s1;
        o.w = S + s2;
        *reinterpret_cast<int4*>(&g_rowstart[base]) = o;
    }
    grid_sync();

    // fill
    const int E4 = E >> 2;
    const int4* rp4 = reinterpret_cast<const int4*>(ei);
    const int4* cp4 = reinterpret_cast<const int4*>(ei + E);
    const int4* rk4 = reinterpret_cast<const int4*>(g_rank);
    for (int q = gid; q < E4; q += nthr) {
        int4 r = __ldg(rp4 + q);
        int4 c = __ldg(cp4 + q);
        int4 k = rk4[q];
        g_ecol[g_rowstart[r.x] + k.x] = c.x;
        g_ecol[g_rowstart[r.y] + k.y] = c.y;
        g_ecol[g_rowstart[r.z] + k.z] = c.z;
        g_ecol[g_rowstart[r.w] + k.w] = c.w;
    }
    for (int e = (E4 << 2) + gid; e < E; e += nthr) {
        int r = __ldg(ei + e);
        g_ecol[g_rowstart[r] + g_rank[e]] = __ldg(ei + E + e);
    }
}

// ---------------------------------------------------------------------------
// GEMM (side stream): xh_h[r] = fp16( rsqrt(deg[r]) * (x[r] @ W^T) )
// ---------------------------------------------------------------------------
#define GEMM_ROWS 32
#define RPT 8
#define GEMM_GRID 296

__global__ void __launch_bounds__(256) k_gemm(const float* __restrict__ x,
                                              const float* __restrict__ W, int N) {
    __shared__ float  Ws[D * (D + 1)];
    __shared__ float2 xs[2][GEMM_ROWS][D / 2];

    int tid = threadIdx.x;
    int tx = tid & 63;
    int ty = tid >> 6;

    for (int i = tid; i < D * D; i += 256)
        Ws[(i >> 6) * (D + 1) + (i & 63)] = W[i];
    __syncthreads();

    unsigned long long w2[D / 2];
#pragma unroll
    for (int k2 = 0; k2 < D / 2; k2++) {
        float2 p = make_float2(Ws[tx * (D + 1) + 2 * k2], Ws[tx * (D + 1) + 2 * k2 + 1]);
        w2[k2] = *reinterpret_cast<unsigned long long*>(&p);
    }
    __syncthreads();

    int ntiles = (N + GEMM_ROWS - 1) / GEMM_ROWS;

    auto issue = [&](int t, int buf) {
        const float4* src = reinterpret_cast<const float4*>(x + (size_t)t * GEMM_ROWS * D);
        int limit = (N - t * GEMM_ROWS) * (D / 4);
        unsigned sbase = smem_u32(&xs[buf][0][0]);
#pragma unroll
        for (int rnd = 0; rnd < 2; rnd++) {
            int v = tid + rnd * 256;
            if (v < 512 && v < limit) cp_async16(sbase + v * 16, src + v);
        }
        cp_commit();
    };

    int t = blockIdx.x;
    if (t < ntiles) issue(t, 0);
    int buf = 0;

    for (; t < ntiles; t += GEMM_GRID) {
        int tn = t + GEMM_GRID;
        bool have_next = (tn < ntiles);
        if (have_next) issue(tn, buf ^ 1);

        if (have_next) cp_wait<1>(); else cp_wait<0>();
        __syncthreads();

        int r0 = ty * RPT;
        unsigned long long acc[RPT];
#pragma unroll
        for (int i = 0; i < RPT; i++) acc[i] = 0ULL;

#pragma unroll
        for (int k2 = 0; k2 < D / 2; k2++) {
            unsigned long long wreg = w2[k2];
#pragma unroll
            for (int i = 0; i < RPT; i++) {
                float2 xv = xs[buf][r0 + i][k2];
                unsigned long long xp = *reinterpret_cast<unsigned long long*>(&xv);
                fma_f32x2(acc[i], xp, wreg, acc[i]);
            }
        }

        int rb = t * GEMM_ROWS;
#pragma unroll
        for (int i = 0; i < RPT; i++) {
            int r = rb + r0 + i;
            if (r < N) {
                float2 p = *reinterpret_cast<float2*>(&acc[i]);
                int dg = g_deg[r];
                float dr = (dg > 0) ? rsqrtf((float)dg) : 0.0f;
                g_xh[(size_t)r * D + tx] = __float2half_rn(dr * (p.x + p.y));
            }
        }
        __syncthreads();
        buf ^= 1;
    }
}

// ---------------------------------------------------------------------------
// Gather: warp per row, fp16 pre-scaled rows.
// ---------------------------------------------------------------------------
__global__ void k_gather(float* __restrict__ out, int N) {
    int gtid = blockIdx.x * blockDim.x + threadIdx.x;
    int warp = gtid >> 5;
    int lane = threadIdx.x & 31;
    int nwarps = (gridDim.x * blockDim.x) >> 5;

    const __half2* xh2 = reinterpret_cast<const __half2*>(g_xh);

    for (int r = warp; r < N; r += nwarps) {
        int s = g_rowstart[r];
        int dg = g_deg[r];
        int e = s + dg;

        float ax = 0.f, ay = 0.f, bx = 0.f, by = 0.f;
        float cx = 0.f, cy = 0.f, dx = 0.f, dy = 0.f;

        int j = s;
        for (; j + 3 < e; j += 4) {
            int c0 = g_ecol[j];
            int c1 = g_ecol[j + 1];
            int c2 = g_ecol[j + 2];
            int c3 = g_ecol[j + 3];
            float2 f0 = __half22float2(xh2[(size_t)c0 * 32 + lane]);
            float2 f1 = __half22float2(xh2[(size_t)c1 * 32 + lane]);
            float2 f2 = __half22float2(xh2[(size_t)c2 * 32 + lane]);
            float2 f3 = __half22float2(xh2[(size_t)c3 * 32 + lane]);
            ax += f0.x; ay += f0.y;
            bx += f1.x; by += f1.y;
            cx += f2.x; cy += f2.y;
            dx += f3.x; dy += f3.y;
        }
        for (; j < e; j++) {
            int c = g_ecol[j];
            float2 f = __half22float2(xh2[(size_t)c * 32 + lane]);
            ax += f.x; ay += f.y;
        }

        float dr = (dg > 0) ? rsqrtf((float)dg) : 0.0f;
        float2 res = make_float2(dr * (ax + bx + cx + dx),
                                 dr * (ay + by + cy + dy));
        reinterpret_cast<float2*>(out)[(size_t)r * 32 + lane] = res;
    }
}

// ---------------------------------------------------------------------------
// launch: kA -> fork(gemm) || kB -> join -> gather      (4 kernels)
// ---------------------------------------------------------------------------
extern "C" void kernel_launch(void* const* d_in, const int* in_sizes, int n_in,
                              void* d_out, int out_size) {
    const int*   edge_index = (const int*)d_in[0];
    const float* x          = (const float*)d_in[1];
    const float* W          = (const float*)d_in[2];
    float*       out        = (float*)d_out;

    int E = in_sizes[0] / 2;
    int N = in_sizes[1] / D;

    k_pre<<<GRID_BUILD, TPB>>>(edge_index, E, N);

    cudaEventRecord(g_ev_deg, 0);
    cudaStreamWaitEvent(g_s1, g_ev_deg, 0);
    k_gemm<<<GEMM_GRID, 256, 0, g_s1>>>(x, W, N);
    cudaEventRecord(g_ev_gemm, g_s1);

    k_csr<<<GRID_BUILD, TPB>>>(edge_index, E, N);

    cudaStreamWaitEvent(0, g_ev_gemm, 0);
    k_gather<<<2048, 256>>>(out, N);
}

// round 15
// speedup vs baseline: 1.6404x; 1.6404x over previous
#include <cuda_runtime.h>
#include <cuda_fp16.h>
#include <cuda_bf16.h>

#define NMAX 100000
#define EMAX 1600000
#define D 64
#define SCAN_B 1024
#define SCAN_MAXBLK 128

// __device__ scratch (no allocations allowed)
__device__ int    g_deg[NMAX];
__device__ int    g_rowstart[NMAX];
__device__ __half g_xh[(size_t)NMAX * D];   // fp16, pre-scaled by dinv[node]
__device__ int    g_ecol[EMAX];             // stores (col << 5): half2-row base offset
__device__ int    g_rank[EMAX];

// decoupled-lookback state: (flag<<32)|value, 8B single-copy-atomic
__device__ volatile unsigned long long g_scan_pair[SCAN_MAXBLK];

// side stream + events (created once at program start; capture-legal fork-join)
static cudaStream_t g_s1;
static cudaEvent_t  g_ev_deg, g_ev_gemm;
namespace {
struct StreamInit {
    StreamInit() {
        cudaStreamCreateWithFlags(&g_s1, cudaStreamNonBlocking);
        cudaEventCreateWithFlags(&g_ev_deg, cudaEventDisableTiming);
        cudaEventCreateWithFlags(&g_ev_gemm, cudaEventDisableTiming);
    }
} g_stream_init;
}

// packed fp32x2 FMA (Blackwell)
__device__ __forceinline__ void fma_f32x2(unsigned long long& d,
                                          unsigned long long a,
                                          unsigned long long b,
                                          unsigned long long c) {
    asm("fma.rn.f32x2 %0, %1, %2, %3;" : "=l"(d) : "l"(a), "l"(b), "l"(c));
}
__device__ __forceinline__ unsigned smem_u32(const void* p) {
    return (unsigned)__cvta_generic_to_shared(p);
}
__device__ __forceinline__ void cp_async16(unsigned s, const void* g) {
    asm volatile("cp.async.cg.shared.global [%0], [%1], 16;" :: "r"(s), "l"(g));
}
__device__ __forceinline__ void cp_commit() { asm volatile("cp.async.commit_group;"); }
template <int N> __device__ __forceinline__ void cp_wait() {
    asm volatile("cp.async.wait_group %0;" :: "n"(N));
}

// ---------------------------------------------------------------------------
// zero degree + scan state
// ---------------------------------------------------------------------------
__global__ void k_zero(int N) {
    int i = blockIdx.x * blockDim.x + threadIdx.x;
    if (i < N) g_deg[i] = 0;
    if (i < SCAN_MAXBLK) g_scan_pair[i] = 0ULL;
}

// ---------------------------------------------------------------------------
// degree histogram + per-edge rank (x4, int4 index loads)
// ---------------------------------------------------------------------------
__global__ void k_degree(const int* __restrict__ rowp, int E) {
    int i = blockIdx.x * blockDim.x + threadIdx.x;
    int stride = gridDim.x * blockDim.x;
    int E4 = E >> 2;
    const int4* rp4 = reinterpret_cast<const int4*>(rowp);
    int4* rk4 = reinterpret_cast<int4*>(g_rank);

    for (int q = i; q < E4; q += stride) {
        int4 r = __ldg(rp4 + q);
        int4 k;
        k.x = atomicAdd(&g_deg[r.x], 1);
        k.y = atomicAdd(&g_deg[r.y], 1);
        k.z = atomicAdd(&g_deg[r.z], 1);
        k.w = atomicAdd(&g_deg[r.w], 1);
        rk4[q] = k;
    }
    for (int e = (E4 << 2) + i; e < E; e += stride)
        g_rank[e] = atomicAdd(&g_deg[__ldg(rowp + e)], 1);
}

// ---------------------------------------------------------------------------
// single-pass scan (warp-parallel decoupled lookback): deg -> exclusive rowstart
// ---------------------------------------------------------------------------
__global__ void __launch_bounds__(SCAN_B) k_scan(int N) {
    __shared__ int wsum[32];
    __shared__ int s_base;

    int bid = blockIdx.x;
    int i = bid * SCAN_B + threadIdx.x;
    int lane = threadIdx.x & 31;
    int wid = threadIdx.x >> 5;

    int v = (i < N) ? g_deg[i] : 0;

    int s = v;
#pragma unroll
    for (int off = 1; off < 32; off <<= 1) {
        int t = __shfl_up_sync(0xffffffffu, s, off);
        if (lane >= off) s += t;
    }
    if (lane == 31) wsum[wid] = s;
    __syncthreads();
    if (wid == 0) {
        int ws = wsum[lane];
#pragma unroll
        for (int off = 1; off < 32; off <<= 1) {
            int t = __shfl_up_sync(0xffffffffu, ws, off);
            if (lane >= off) ws += t;
        }
        wsum[lane] = ws;
    }
    __syncthreads();
    int incl = s + ((wid > 0) ? wsum[wid - 1] : 0);
    int block_total = wsum[31];

    if (wid == 0) {
        if (bid == 0) {
            if (lane == 0) {
                g_scan_pair[0] = (2ULL << 32) | (unsigned)block_total;
                s_base = 0;
            }
        } else {
            if (lane == 0)
                g_scan_pair[bid] = (1ULL << 32) | (unsigned)block_total;
            __syncwarp();

            int base = 0;
            int wstart = bid - 1;
            while (true) {
                int j = wstart - lane;
                unsigned flag = 0, val = 0;
                if (j >= 0) {
                    unsigned long long p;
                    do { p = g_scan_pair[j]; } while ((p >> 32) == 0ULL);
                    flag = (unsigned)(p >> 32);
                    val = (unsigned)p;
                }
                unsigned b2 = __ballot_sync(0xffffffffu, flag == 2u);
                if (b2) {
                    int lp = __ffs(b2) - 1;
                    unsigned contrib = (lane <= lp) ? val : 0u;
                    base += (int)__reduce_add_sync(0xffffffffu, contrib);
                    break;
                } else {
                    base += (int)__reduce_add_sync(0xffffffffu, val);
                    wstart -= 32;
                }
            }
            if (lane == 0) {
                g_scan_pair[bid] = (2ULL << 32) | (unsigned)(base + block_total);
                s_base = base;
            }
        }
    }
    __syncthreads();

    if (i < N) g_rowstart[i] = s_base + incl - v;
}

// ---------------------------------------------------------------------------
// CSR fill: no atomics; stores PRE-SHIFTED col offsets (c<<5 = half2-row base)
// ---------------------------------------------------------------------------
__global__ void k_fill(const int* __restrict__ ei, int E) {
    int i = blockIdx.x * blockDim.x + threadIdx.x;
    int stride = gridDim.x * blockDim.x;
    int E4 = E >> 2;
    const int4* rp4 = reinterpret_cast<const int4*>(ei);
    const int4* cp4 = reinterpret_cast<const int4*>(ei + E);
    const int4* rk4 = reinterpret_cast<const int4*>(g_rank);

    for (int q = i; q < E4; q += stride) {
        int4 r = __ldg(rp4 + q);
        int4 c = __ldg(cp4 + q);
        int4 k = rk4[q];
        g_ecol[g_rowstart[r.x] + k.x] = c.x << 5;
        g_ecol[g_rowstart[r.y] + k.y] = c.y << 5;
        g_ecol[g_rowstart[r.z] + k.z] = c.z << 5;
        g_ecol[g_rowstart[r.w] + k.w] = c.w << 5;
    }
    for (int e = (E4 << 2) + i; e < E; e += stride) {
        int r = __ldg(ei + e);
        int c = __ldg(ei + E + e);
        g_ecol[g_rowstart[r] + g_rank[e]] = c << 5;
    }
}

// ---------------------------------------------------------------------------
// GEMM (side stream): xh_h[r] = fp16( rsqrt(deg[r]) * (x[r] @ W^T) )
// ---------------------------------------------------------------------------
#define GEMM_ROWS 32
#define RPT 8
#define GEMM_GRID 296

__global__ void __launch_bounds__(256) k_gemm(const float* __restrict__ x,
                                              const float* __restrict__ W, int N) {
    __shared__ float  Ws[D * (D + 1)];
    __shared__ float2 xs[2][GEMM_ROWS][D / 2];

    int tid = threadIdx.x;
    int tx = tid & 63;
    int ty = tid >> 6;

    for (int i = tid; i < D * D; i += 256)
        Ws[(i >> 6) * (D + 1) + (i & 63)] = W[i];
    __syncthreads();

    unsigned long long w2[D / 2];
#pragma unroll
    for (int k2 = 0; k2 < D / 2; k2++) {
        float2 p = make_float2(Ws[tx * (D + 1) + 2 * k2], Ws[tx * (D + 1) + 2 * k2 + 1]);
        w2[k2] = *reinterpret_cast<unsigned long long*>(&p);
    }
    __syncthreads();

    int ntiles = (N + GEMM_ROWS - 1) / GEMM_ROWS;

    auto issue = [&](int t, int buf) {
        const float4* src = reinterpret_cast<const float4*>(x + (size_t)t * GEMM_ROWS * D);
        int limit = (N - t * GEMM_ROWS) * (D / 4);
        unsigned sbase = smem_u32(&xs[buf][0][0]);
#pragma unroll
        for (int rnd = 0; rnd < 2; rnd++) {
            int v = tid + rnd * 256;
            if (v < 512 && v < limit) cp_async16(sbase + v * 16, src + v);
        }
        cp_commit();
    };

    int t = blockIdx.x;
    if (t < ntiles) issue(t, 0);
    int buf = 0;

    for (; t < ntiles; t += GEMM_GRID) {
        int tn = t + GEMM_GRID;
        bool have_next = (tn < ntiles);
        if (have_next) issue(tn, buf ^ 1);

        if (have_next) cp_wait<1>(); else cp_wait<0>();
        __syncthreads();

        int r0 = ty * RPT;
        unsigned long long acc[RPT];
#pragma unroll
        for (int i = 0; i < RPT; i++) acc[i] = 0ULL;

#pragma unroll
        for (int k2 = 0; k2 < D / 2; k2++) {
            unsigned long long wreg = w2[k2];
#pragma unroll
            for (int i = 0; i < RPT; i++) {
                float2 xv = xs[buf][r0 + i][k2];
                unsigned long long xp = *reinterpret_cast<unsigned long long*>(&xv);
                fma_f32x2(acc[i], xp, wreg, acc[i]);
            }
        }

        int rb = t * GEMM_ROWS;
#pragma unroll
        for (int i = 0; i < RPT; i++) {
            int r = rb + r0 + i;
            if (r < N) {
                float2 p = *reinterpret_cast<float2*>(&acc[i]);
                int dg = g_deg[r];
                float dr = (dg > 0) ? rsqrtf((float)dg) : 0.0f;
                g_xh[(size_t)r * D + tx] = __float2half_rn(dr * (p.x + p.y));
            }
        }
        __syncthreads();
        buf ^= 1;
    }
}

// ---------------------------------------------------------------------------
// Gather: warp per row, instruction-lean. ecol holds pre-shifted half2-row
// offsets -> per-edge address is one IADD. All index math 32-bit.
// ---------------------------------------------------------------------------
__global__ void __launch_bounds__(256) k_gather(float* __restrict__ out, int N) {
    int gtid = blockIdx.x * blockDim.x + threadIdx.x;
    int warp = gtid >> 5;
    int lane = threadIdx.x & 31;
    int nwarps = (gridDim.x * blockDim.x) >> 5;

    const __half2* __restrict__ xh2 = reinterpret_cast<const __half2*>(g_xh);

    for (int r = warp; r < N; r += nwarps) {
        int s = g_rowstart[r];
        int dg = g_deg[r];
        int e = s + dg;

        float ax = 0.f, ay = 0.f, bx = 0.f, by = 0.f;
        float cx = 0.f, cy = 0.f, dx = 0.f, dy = 0.f;

        int j = s;
        for (; j + 3 < e; j += 4) {
            int o0 = g_ecol[j]     + lane;   // pre-shifted: 1 IADD each
            int o1 = g_ecol[j + 1] + lane;
            int o2 = g_ecol[j + 2] + lane;
            int o3 = g_ecol[j + 3] + lane;
            float2 f0 = __half22float2(xh2[o0]);
            float2 f1 = __half22float2(xh2[o1]);
            float2 f2 = __half22float2(xh2[o2]);
            float2 f3 = __half22float2(xh2[o3]);
            ax += f0.x; ay += f0.y;
            bx += f1.x; by += f1.y;
            cx += f2.x; cy += f2.y;
            dx += f3.x; dy += f3.y;
        }
        for (; j < e; j++) {
            float2 f = __half22float2(xh2[g_ecol[j] + lane]);
            ax += f.x; ay += f.y;
        }

        float dr = (dg > 0) ? rsqrtf((float)dg) : 0.0f;
        float2 res = make_float2(dr * ((ax + bx) + (cx + dx)),
                                 dr * ((ay + by) + (cy + dy)));
        reinterpret_cast<float2*>(out)[(size_t)r * 32 + lane] = res;
    }
}

// ---------------------------------------------------------------------------
// launch: R11 structure (fork gemm after degree; join before gather)
// ---------------------------------------------------------------------------
extern "C" void kernel_launch(void* const* d_in, const int* in_sizes, int n_in,
                              void* d_out, int out_size) {
    const int*   edge_index = (const int*)d_in[0];
    const float* x          = (const float*)d_in[1];
    const float* W          = (const float*)d_in[2];
    float*       out        = (float*)d_out;

    int E = in_sizes[0] / 2;
    int N = in_sizes[1] / D;
    int nb = (N + SCAN_B - 1) / SCAN_B;   // 98 for N=100000

    k_zero<<<(N + 255) / 256, 256>>>(N);
    k_degree<<<1024, 256>>>(edge_index, E);

    cudaEventRecord(g_ev_deg, 0);
    cudaStreamWaitEvent(g_s1, g_ev_deg, 0);
    k_gemm<<<GEMM_GRID, 256, 0, g_s1>>>(x, W, N);
    cudaEventRecord(g_ev_gemm, g_s1);

    k_scan<<<nb, SCAN_B>>>(N);
    k_fill<<<1024, 256>>>(edge_index, E);

    cudaStreamWaitEvent(0, g_ev_gemm, 0);
    k_gather<<<2048, 256>>>(out, N);
}

// round 16
// speedup vs baseline: 1.6439x; 1.0021x over previous
#include <cuda_runtime.h>
#include <cuda_fp16.h>
#include <cuda_bf16.h>

#define NMAX 100000
#define EMAX 1600000
#define EPAD (EMAX + 4 * NMAX)     // padded CSR upper bound (E + 3N rounded up)
#define D 64
#define SCAN_B 1024
#define SCAN_MAXBLK 128
#define ZERO_OFF (NMAX << 5)       // pre-shifted offset of the always-zero xh row

// __device__ scratch (no allocations allowed)
__device__ int    g_deg[NMAX];
__device__ int    g_rowstart[NMAX];           // PADDED exclusive prefix (multiple of 4)
__device__ __half g_xh[(size_t)(NMAX + 1) * D]; // row NMAX stays zero forever (pads)
__device__ int    g_ecol[EPAD];               // pre-shifted col offsets (c<<5)
__device__ int    g_rank[EMAX];

// decoupled-lookback state: (flag<<32)|value, 8B single-copy-atomic
__device__ volatile unsigned long long g_scan_pair[SCAN_MAXBLK];

// side stream + events (created once at program start; capture-legal fork-join)
static cudaStream_t g_s1;
static cudaEvent_t  g_ev_deg, g_ev_gemm;
namespace {
struct StreamInit {
    StreamInit() {
        cudaStreamCreateWithFlags(&g_s1, cudaStreamNonBlocking);
        cudaEventCreateWithFlags(&g_ev_deg, cudaEventDisableTiming);
        cudaEventCreateWithFlags(&g_ev_gemm, cudaEventDisableTiming);
    }
} g_stream_init;
}

// packed fp32x2 FMA (Blackwell)
__device__ __forceinline__ void fma_f32x2(unsigned long long& d,
                                          unsigned long long a,
                                          unsigned long long b,
                                          unsigned long long c) {
    asm("fma.rn.f32x2 %0, %1, %2, %3;" : "=l"(d) : "l"(a), "l"(b), "l"(c));
}
__device__ __forceinline__ unsigned smem_u32(const void* p) {
    return (unsigned)__cvta_generic_to_shared(p);
}
__device__ __forceinline__ void cp_async16(unsigned s, const void* g) {
    asm volatile("cp.async.cg.shared.global [%0], [%1], 16;" :: "r"(s), "l"(g));
}
__device__ __forceinline__ void cp_commit() { asm volatile("cp.async.commit_group;"); }
template <int N> __device__ __forceinline__ void cp_wait() {
    asm volatile("cp.async.wait_group %0;" :: "n"(N));
}

// ---------------------------------------------------------------------------
// zero degree + scan state
// ---------------------------------------------------------------------------
__global__ void k_zero(int N) {
    int i = blockIdx.x * blockDim.x + threadIdx.x;
    if (i < N) g_deg[i] = 0;
    if (i < SCAN_MAXBLK) g_scan_pair[i] = 0ULL;
}

// ---------------------------------------------------------------------------
// degree histogram + per-edge rank (x4, int4 index loads)
// ---------------------------------------------------------------------------
__global__ void k_degree(const int* __restrict__ rowp, int E) {
    int i = blockIdx.x * blockDim.x + threadIdx.x;
    int stride = gridDim.x * blockDim.x;
    int E4 = E >> 2;
    const int4* rp4 = reinterpret_cast<const int4*>(rowp);
    int4* rk4 = reinterpret_cast<int4*>(g_rank);

    for (int q = i; q < E4; q += stride) {
        int4 r = __ldg(rp4 + q);
        int4 k;
        k.x = atomicAdd(&g_deg[r.x], 1);
        k.y = atomicAdd(&g_deg[r.y], 1);
        k.z = atomicAdd(&g_deg[r.z], 1);
        k.w = atomicAdd(&g_deg[r.w], 1);
        rk4[q] = k;
    }
    for (int e = (E4 << 2) + i; e < E; e += stride)
        g_rank[e] = atomicAdd(&g_deg[__ldg(rowp + e)], 1);
}

// ---------------------------------------------------------------------------
// single-pass scan over PADDED degrees ((deg+3)&~3): rowstart multiple of 4
// ---------------------------------------------------------------------------
__global__ void __launch_bounds__(SCAN_B) k_scan(int N) {
    __shared__ int wsum[32];
    __shared__ int s_base;

    int bid = blockIdx.x;
    int i = bid * SCAN_B + threadIdx.x;
    int lane = threadIdx.x & 31;
    int wid = threadIdx.x >> 5;

    int v = (i < N) ? ((g_deg[i] + 3) & ~3) : 0;   // padded degree

    int s = v;
#pragma unroll
    for (int off = 1; off < 32; off <<= 1) {
        int t = __shfl_up_sync(0xffffffffu, s, off);
        if (lane >= off) s += t;
    }
    if (lane == 31) wsum[wid] = s;
    __syncthreads();
    if (wid == 0) {
        int ws = wsum[lane];
#pragma unroll
        for (int off = 1; off < 32; off <<= 1) {
            int t = __shfl_up_sync(0xffffffffu, ws, off);
            if (lane >= off) ws += t;
        }
        wsum[lane] = ws;
    }
    __syncthreads();
    int incl = s + ((wid > 0) ? wsum[wid - 1] : 0);
    int block_total = wsum[31];

    if (wid == 0) {
        if (bid == 0) {
            if (lane == 0) {
                g_scan_pair[0] = (2ULL << 32) | (unsigned)block_total;
                s_base = 0;
            }
        } else {
            if (lane == 0)
                g_scan_pair[bid] = (1ULL << 32) | (unsigned)block_total;
            __syncwarp();

            int base = 0;
            int wstart = bid - 1;
            while (true) {
                int j = wstart - lane;
                unsigned flag = 0, val = 0;
                if (j >= 0) {
                    unsigned long long p;
                    do { p = g_scan_pair[j]; } while ((p >> 32) == 0ULL);
                    flag = (unsigned)(p >> 32);
                    val = (unsigned)p;
                }
                unsigned b2 = __ballot_sync(0xffffffffu, flag == 2u);
                if (b2) {
                    int lp = __ffs(b2) - 1;
                    unsigned contrib = (lane <= lp) ? val : 0u;
                    base += (int)__reduce_add_sync(0xffffffffu, contrib);
                    break;
                } else {
                    base += (int)__reduce_add_sync(0xffffffffu, val);
                    wstart -= 32;
                }
            }
            if (lane == 0) {
                g_scan_pair[bid] = (2ULL << 32) | (unsigned)(base + block_total);
                s_base = base;
            }
        }
    }
    __syncthreads();

    if (i < N) g_rowstart[i] = s_base + incl - v;
}

// ---------------------------------------------------------------------------
// CSR fill: real edges via rowstart+rank (pre-shifted cols), then pad each
// row to a multiple of 4 with offsets to the always-zero xh row.
// ---------------------------------------------------------------------------
__global__ void k_fill(const int* __restrict__ ei, int E, int N) {
    int i = blockIdx.x * blockDim.x + threadIdx.x;
    int stride = gridDim.x * blockDim.x;
    int E4 = E >> 2;
    const int4* rp4 = reinterpret_cast<const int4*>(ei);
    const int4* cp4 = reinterpret_cast<const int4*>(ei + E);
    const int4* rk4 = reinterpret_cast<const int4*>(g_rank);

    for (int q = i; q < E4; q += stride) {
        int4 r = __ldg(rp4 + q);
        int4 c = __ldg(cp4 + q);
        int4 k = rk4[q];
        g_ecol[g_rowstart[r.x] + k.x] = c.x << 5;
        g_ecol[g_rowstart[r.y] + k.y] = c.y << 5;
        g_ecol[g_rowstart[r.z] + k.z] = c.z << 5;
        g_ecol[g_rowstart[r.w] + k.w] = c.w << 5;
    }
    for (int e = (E4 << 2) + i; e < E; e += stride) {
        int r = __ldg(ei + e);
        int c = __ldg(ei + E + e);
        g_ecol[g_rowstart[r] + g_rank[e]] = c << 5;
    }

    // pad slots (disjoint positions from real edges; no barrier needed)
    for (int r = i; r < N; r += stride) {
        int dg = g_deg[r];
        int pad = ((dg + 3) & ~3) - dg;          // 0..3
        if (pad) {
            int base = g_rowstart[r] + dg;
            for (int p = 0; p < pad; p++) g_ecol[base + p] = ZERO_OFF;
        }
    }
}

// ---------------------------------------------------------------------------
// GEMM (side stream): xh_h[r] = fp16( rsqrt(deg[r]) * (x[r] @ W^T) )
// (never writes row NMAX -> it stays zero)
// ---------------------------------------------------------------------------
#define GEMM_ROWS 32
#define RPT 8
#define GEMM_GRID 296

__global__ void __launch_bounds__(256) k_gemm(const float* __restrict__ x,
                                              const float* __restrict__ W, int N) {
    __shared__ float  Ws[D * (D + 1)];
    __shared__ float2 xs[2][GEMM_ROWS][D / 2];

    int tid = threadIdx.x;
    int tx = tid & 63;
    int ty = tid >> 6;

    for (int i = tid; i < D * D; i += 256)
        Ws[(i >> 6) * (D + 1) + (i & 63)] = W[i];
    __syncthreads();

    unsigned long long w2[D / 2];
#pragma unroll
    for (int k2 = 0; k2 < D / 2; k2++) {
        float2 p = make_float2(Ws[tx * (D + 1) + 2 * k2], Ws[tx * (D + 1) + 2 * k2 + 1]);
        w2[k2] = *reinterpret_cast<unsigned long long*>(&p);
    }
    __syncthreads();

    int ntiles = (N + GEMM_ROWS - 1) / GEMM_ROWS;

    auto issue = [&](int t, int buf) {
        const float4* src = reinterpret_cast<const float4*>(x + (size_t)t * GEMM_ROWS * D);
        int limit = (N - t * GEMM_ROWS) * (D / 4);
        unsigned sbase = smem_u32(&xs[buf][0][0]);
#pragma unroll
        for (int rnd = 0; rnd < 2; rnd++) {
            int v = tid + rnd * 256;
            if (v < 512 && v < limit) cp_async16(sbase + v * 16, src + v);
        }
        cp_commit();
    };

    int t = blockIdx.x;
    if (t < ntiles) issue(t, 0);
    int buf = 0;

    for (; t < ntiles; t += GEMM_GRID) {
        int tn = t + GEMM_GRID;
        bool have_next = (tn < ntiles);
        if (have_next) issue(tn, buf ^ 1);

        if (have_next) cp_wait<1>(); else cp_wait<0>();
        __syncthreads();

        int r0 = ty * RPT;
        unsigned long long acc[RPT];
#pragma unroll
        for (int i = 0; i < RPT; i++) acc[i] = 0ULL;

#pragma unroll
        for (int k2 = 0; k2 < D / 2; k2++) {
            unsigned long long wreg = w2[k2];
#pragma unroll
            for (int i = 0; i < RPT; i++) {
                float2 xv = xs[buf][r0 + i][k2];
                unsigned long long xp = *reinterpret_cast<unsigned long long*>(&xv);
                fma_f32x2(acc[i], xp, wreg, acc[i]);
            }
        }

        int rb = t * GEMM_ROWS;
#pragma unroll
        for (int i = 0; i < RPT; i++) {
            int r = rb + r0 + i;
            if (r < N) {
                float2 p = *reinterpret_cast<float2*>(&acc[i]);
                int dg = g_deg[r];
                float dr = (dg > 0) ? rsqrtf((float)dg) : 0.0f;
                g_xh[(size_t)r * D + tx] = __float2half_rn(dr * (p.x + p.y));
            }
        }
        __syncthreads();
        buf ^= 1;
    }
}

// ---------------------------------------------------------------------------
// Gather: warp per row, branch-free. Row length is a multiple of 4 and the
// start is 16B-aligned, so the loop is: ONE uniform int4 load of 4 pre-shifted
// offsets + 4 coalesced LDG.64 + 8 FADD. Pads hit the zero row (add 0.0f).
// ---------------------------------------------------------------------------
__global__ void __launch_bounds__(256) k_gather(float* __restrict__ out, int N) {
    int gtid = blockIdx.x * blockDim.x + threadIdx.x;
    int warp = gtid >> 5;
    int lane = threadIdx.x & 31;
    int nwarps = (gridDim.x * blockDim.x) >> 5;

    const __half2* __restrict__ xh2 = reinterpret_cast<const __half2*>(g_xh);
    const int4* __restrict__ cc4 = reinterpret_cast<const int4*>(g_ecol);

    for (int r = warp; r < N; r += nwarps) {
        int s = g_rowstart[r];           // multiple of 4
        int dg = g_deg[r];
        int q0 = s >> 2;
        int q1 = (s + ((dg + 3) & ~3)) >> 2;

        float ax = 0.f, ay = 0.f, bx = 0.f, by = 0.f;
        float cx = 0.f, cy = 0.f, dx = 0.f, dy = 0.f;

        for (int q = q0; q < q1; q++) {
            int4 c = cc4[q];             // uniform 16B load: 4 edge offsets
            float2 f0 = __half22float2(xh2[c.x + lane]);
            float2 f1 = __half22float2(xh2[c.y + lane]);
            float2 f2 = __half22float2(xh2[c.z + lane]);
            float2 f3 = __half22float2(xh2[c.w + lane]);
            ax += f0.x; ay += f0.y;
            bx += f1.x; by += f1.y;
            cx += f2.x; cy += f2.y;
            dx += f3.x; dy += f3.y;
        }

        float dr = (dg > 0) ? rsqrtf((float)dg) : 0.0f;
        float2 res = make_float2(dr * ((ax + bx) + (cx + dx)),
                                 dr * ((ay + by) + (cy + dy)));
        reinterpret_cast<float2*>(out)[(size_t)r * 32 + lane] = res;
    }
}

// ---------------------------------------------------------------------------
// launch: fork gemm after degree; join before gather
// ---------------------------------------------------------------------------
extern "C" void kernel_launch(void* const* d_in, const int* in_sizes, int n_in,
                              void* d_out, int out_size) {
    const int*   edge_index = (const int*)d_in[0];
    const float* x          = (const float*)d_in[1];
    const float* W          = (const float*)d_in[2];
    float*       out        = (float*)d_out;

    int E = in_sizes[0] / 2;
    int N = in_sizes[1] / D;
    int nb = (N + SCAN_B - 1) / SCAN_B;   // 98 for N=100000

    k_zero<<<(N + 255) / 256, 256>>>(N);
    k_degree<<<1024, 256>>>(edge_index, E);

    cudaEventRecord(g_ev_deg, 0);
    cudaStreamWaitEvent(g_s1, g_ev_deg, 0);
    k_gemm<<<GEMM_GRID, 256, 0, g_s1>>>(x, W, N);
    cudaEventRecord(g_ev_gemm, g_s1);

    k_scan<<<nb, SCAN_B>>>(N);
    k_fill<<<1024, 256>>>(edge_index, E, N);

    cudaStreamWaitEvent(0, g_ev_gemm, 0);
    k_gather<<<2048, 256>>>(out, N);
}